// round 1
// baseline (speedup 1.0000x reference)
#include <cuda_runtime.h>
#include <cstddef>

#define D_MODEL 512
#define NHEAD   8
#define DH      64
#define BATCH   2
#define SEQ     2048
#define NTOK    (BATCH*SEQ)   // 4096

static const int       OUT_ELEMS  = NTOK * D_MODEL;                       // 2,097,152
static const long long ATTN_ELEMS = (long long)BATCH*NHEAD*SEQ*SEQ;       // 67,108,864

// Scratch (allocation-free rule: __device__ globals)
__device__ float g_Q[NTOK*D_MODEL];
__device__ float g_K[NTOK*D_MODEL];
__device__ float g_V[NTOK*D_MODEL];
__device__ float g_X[NTOK*D_MODEL];
__device__ float g_attn_fallback[(size_t)BATCH*NHEAD*SEQ*SEQ];

// ---------------------------------------------------------------------------
// Generic 128x128 tile SGEMM body: Y[m,n] = sum_k X[m,k]*W[n,k] + bias[n]
// (both operands K-contiguous; this matches x @ W.T + b)
// 256 threads, 8x8 micro-tile per thread, BK=8.
// ---------------------------------------------------------------------------
__device__ __forceinline__ void gemm128_body(
    const float* __restrict__ X, const float* __restrict__ W,
    const float* __restrict__ bias, float* __restrict__ Y,
    int K, int ldx, int ldw, int ldy, int m0, int n0)
{
    __shared__ float As[8][128];
    __shared__ float Bs[8][128];
    const int tid  = threadIdx.x;
    const int tx   = tid & 15;
    const int ty   = tid >> 4;
    const int lrow = tid >> 1;
    const int lk4  = (tid & 1) * 4;

    float acc[8][8];
#pragma unroll
    for (int i = 0; i < 8; i++)
#pragma unroll
        for (int j = 0; j < 8; j++) acc[i][j] = 0.f;

    for (int k0 = 0; k0 < K; k0 += 8) {
        float4 av = *reinterpret_cast<const float4*>(&X[(size_t)(m0+lrow)*ldx + k0 + lk4]);
        float4 bv = *reinterpret_cast<const float4*>(&W[(size_t)(n0+lrow)*ldw + k0 + lk4]);
        As[lk4+0][lrow]=av.x; As[lk4+1][lrow]=av.y; As[lk4+2][lrow]=av.z; As[lk4+3][lrow]=av.w;
        Bs[lk4+0][lrow]=bv.x; Bs[lk4+1][lrow]=bv.y; Bs[lk4+2][lrow]=bv.z; Bs[lk4+3][lrow]=bv.w;
        __syncthreads();
#pragma unroll
        for (int kk = 0; kk < 8; kk++) {
            float a[8], b[8];
#pragma unroll
            for (int i = 0; i < 8; i++) a[i] = As[kk][ty*8+i];
#pragma unroll
            for (int j = 0; j < 8; j++) b[j] = Bs[kk][tx*8+j];
#pragma unroll
            for (int i = 0; i < 8; i++)
#pragma unroll
                for (int j = 0; j < 8; j++) acc[i][j] = fmaf(a[i], b[j], acc[i][j]);
        }
        __syncthreads();
    }
#pragma unroll
    for (int i = 0; i < 8; i++) {
        int row = m0 + ty*8 + i;
#pragma unroll
        for (int j = 0; j < 8; j++) {
            int col = n0 + tx*8 + j;
            Y[(size_t)row*ldy + col] = acc[i][j] + bias[col];
        }
    }
}

// QKV projections in one launch (z selects which)
__global__ void __launch_bounds__(256)
qkv_proj_kernel(const float* __restrict__ q_in, const float* __restrict__ k_in,
                const float* __restrict__ v_in,
                const float* __restrict__ Wq, const float* __restrict__ bq,
                const float* __restrict__ Wk, const float* __restrict__ bk,
                const float* __restrict__ Wv, const float* __restrict__ bv)
{
    const float* X; const float* W; const float* bias; float* Y;
    if (blockIdx.z == 0)      { X = q_in; W = Wq; bias = bq; Y = g_Q; }
    else if (blockIdx.z == 1) { X = k_in; W = Wk; bias = bk; Y = g_K; }
    else                      { X = v_in; W = Wv; bias = bv; Y = g_V; }
    gemm128_body(X, W, bias, Y, D_MODEL, D_MODEL, D_MODEL, D_MODEL,
                 blockIdx.y*128, blockIdx.x*128);
}

// Output projection: out = X @ Wo.T + bo
__global__ void __launch_bounds__(256)
oproj_kernel(const float* __restrict__ Wo, const float* __restrict__ bo,
             float* __restrict__ out)
{
    gemm128_body(g_X, Wo, bo, out, D_MODEL, D_MODEL, D_MODEL, D_MODEL,
                 blockIdx.y*128, blockIdx.x*128);
}

// ---------------------------------------------------------------------------
// Scores: dots[bh,i,j] = 0.125 * sum_d Q[b,i,h*64+d]*K[b,j,h*64+d], masked.
// 128x128 tile per block over (i,j); K=64.
// ---------------------------------------------------------------------------
__global__ void __launch_bounds__(256)
score_kernel(const int* __restrict__ mask, float* attn_arg)
{
    float* attn = attn_arg ? attn_arg : g_attn_fallback;
    const int bh = blockIdx.z, b = bh >> 3, h = bh & 7;
    const float* Qb = g_Q + (size_t)b*SEQ*D_MODEL + h*DH;
    const float* Kb = g_K + (size_t)b*SEQ*D_MODEL + h*DH;
    const int m0 = blockIdx.y*128, n0 = blockIdx.x*128;

    __shared__ float As[8][128];
    __shared__ float Bs[8][128];
    const int tid  = threadIdx.x;
    const int tx   = tid & 15;
    const int ty   = tid >> 4;
    const int lrow = tid >> 1;
    const int lk4  = (tid & 1) * 4;

    float acc[8][8];
#pragma unroll
    for (int i = 0; i < 8; i++)
#pragma unroll
        for (int j = 0; j < 8; j++) acc[i][j] = 0.f;

    for (int k0 = 0; k0 < DH; k0 += 8) {
        float4 av = *reinterpret_cast<const float4*>(&Qb[(size_t)(m0+lrow)*D_MODEL + k0 + lk4]);
        float4 bv = *reinterpret_cast<const float4*>(&Kb[(size_t)(n0+lrow)*D_MODEL + k0 + lk4]);
        As[lk4+0][lrow]=av.x; As[lk4+1][lrow]=av.y; As[lk4+2][lrow]=av.z; As[lk4+3][lrow]=av.w;
        Bs[lk4+0][lrow]=bv.x; Bs[lk4+1][lrow]=bv.y; Bs[lk4+2][lrow]=bv.z; Bs[lk4+3][lrow]=bv.w;
        __syncthreads();
#pragma unroll
        for (int kk = 0; kk < 8; kk++) {
            float a[8], bb[8];
#pragma unroll
            for (int i = 0; i < 8; i++) a[i]  = As[kk][ty*8+i];
#pragma unroll
            for (int j = 0; j < 8; j++) bb[j] = Bs[kk][tx*8+j];
#pragma unroll
            for (int i = 0; i < 8; i++)
#pragma unroll
                for (int j = 0; j < 8; j++) acc[i][j] = fmaf(a[i], bb[j], acc[i][j]);
        }
        __syncthreads();
    }

    int mv[8];
#pragma unroll
    for (int j = 0; j < 8; j++) mv[j] = mask[b*SEQ + n0 + tx*8 + j];

#pragma unroll
    for (int i = 0; i < 8; i++) {
        int row = m0 + ty*8 + i;
        float* dst = attn + ((size_t)bh*SEQ + row)*SEQ;
#pragma unroll
        for (int j = 0; j < 8; j++) {
            int col = n0 + tx*8 + j;
            float v = acc[i][j] * 0.125f;
            if (mv[j] == 0) v = -1.0e9f;
            dst[col] = v;
        }
    }
}

// ---------------------------------------------------------------------------
// Row softmax in place: one block per row of 2048, 256 threads x 8 elems.
// ---------------------------------------------------------------------------
__global__ void __launch_bounds__(256)
softmax_kernel(float* attn_arg)
{
    float* attn = attn_arg ? attn_arg : g_attn_fallback;
    __shared__ float red[8];
    const size_t row = blockIdx.x;
    float* p = attn + row * (size_t)SEQ;
    const int tid = threadIdx.x;

    float4 v0 = reinterpret_cast<float4*>(p)[2*tid + 0];
    float4 v1 = reinterpret_cast<float4*>(p)[2*tid + 1];

    float m = fmaxf(fmaxf(fmaxf(v0.x,v0.y), fmaxf(v0.z,v0.w)),
                    fmaxf(fmaxf(v1.x,v1.y), fmaxf(v1.z,v1.w)));
#pragma unroll
    for (int o = 16; o; o >>= 1) m = fmaxf(m, __shfl_xor_sync(0xffffffffu, m, o));
    if ((tid & 31) == 0) red[tid >> 5] = m;
    __syncthreads();
    m = red[0];
#pragma unroll
    for (int w = 1; w < 8; w++) m = fmaxf(m, red[w]);
    __syncthreads();

    v0.x = expf(v0.x - m); v0.y = expf(v0.y - m); v0.z = expf(v0.z - m); v0.w = expf(v0.w - m);
    v1.x = expf(v1.x - m); v1.y = expf(v1.y - m); v1.z = expf(v1.z - m); v1.w = expf(v1.w - m);

    float s = v0.x + v0.y + v0.z + v0.w + v1.x + v1.y + v1.z + v1.w;
#pragma unroll
    for (int o = 16; o; o >>= 1) s += __shfl_xor_sync(0xffffffffu, s, o);
    if ((tid & 31) == 0) red[tid >> 5] = s;
    __syncthreads();
    s = red[0];
#pragma unroll
    for (int w = 1; w < 8; w++) s += red[w];

    const float inv = 1.0f / s;
    v0.x *= inv; v0.y *= inv; v0.z *= inv; v0.w *= inv;
    v1.x *= inv; v1.y *= inv; v1.z *= inv; v1.w *= inv;
    reinterpret_cast<float4*>(p)[2*tid + 0] = v0;
    reinterpret_cast<float4*>(p)[2*tid + 1] = v1;
}

// ---------------------------------------------------------------------------
// PV: X[b,i,h*64+d] = sum_j attn[bh,i,j] * V[b,j,h*64+d]
// 128 rows x 64 cols tile, BK=16. 256 threads, 8x4 micro-tile.
// ---------------------------------------------------------------------------
__global__ void __launch_bounds__(256)
pv_kernel(const float* attn_arg)
{
    const float* attn = attn_arg ? attn_arg : g_attn_fallback;
    const int bh = blockIdx.y, b = bh >> 3, h = bh & 7;
    const int m0 = blockIdx.x * 128;

    __shared__ float As[16][128];
    __shared__ float Bs[16][64];
    const int tid = threadIdx.x;
    const int tx  = tid & 15;
    const int ty  = tid >> 4;

    float acc[8][4];
#pragma unroll
    for (int i = 0; i < 8; i++)
#pragma unroll
        for (int j = 0; j < 4; j++) acc[i][j] = 0.f;

    const float* Ab = attn + ((size_t)bh*SEQ + m0) * SEQ;
    const float* Vb = g_V + (size_t)b*SEQ*D_MODEL + h*DH;

    for (int j0 = 0; j0 < SEQ; j0 += 16) {
        // A tile: 128 rows x 16 cols = 512 float4, 2 per thread
#pragma unroll
        for (int r = 0; r < 2; r++) {
            int idx = tid + r*256;
            int ar  = idx >> 2;
            int af  = idx & 3;
            float4 v = *reinterpret_cast<const float4*>(&Ab[(size_t)ar*SEQ + j0 + af*4]);
            As[af*4+0][ar]=v.x; As[af*4+1][ar]=v.y; As[af*4+2][ar]=v.z; As[af*4+3][ar]=v.w;
        }
        // B tile: 16 rows x 64 cols = 256 float4, 1 per thread
        {
            int br = tid >> 4;
            int bf = tid & 15;
            float4 v = *reinterpret_cast<const float4*>(&Vb[(size_t)(j0+br)*D_MODEL + bf*4]);
            Bs[br][bf*4+0]=v.x; Bs[br][bf*4+1]=v.y; Bs[br][bf*4+2]=v.z; Bs[br][bf*4+3]=v.w;
        }
        __syncthreads();
#pragma unroll
        for (int kk = 0; kk < 16; kk++) {
            float a[8], bb[4];
#pragma unroll
            for (int i = 0; i < 8; i++) a[i]  = As[kk][ty*8+i];
#pragma unroll
            for (int j = 0; j < 4; j++) bb[j] = Bs[kk][tx*4+j];
#pragma unroll
            for (int i = 0; i < 8; i++)
#pragma unroll
                for (int j = 0; j < 4; j++) acc[i][j] = fmaf(a[i], bb[j], acc[i][j]);
        }
        __syncthreads();
    }

#pragma unroll
    for (int i = 0; i < 8; i++) {
        int row = m0 + ty*8 + i;
#pragma unroll
        for (int j = 0; j < 4; j++)
            g_X[(size_t)(b*SEQ + row)*D_MODEL + h*DH + tx*4 + j] = acc[i][j];
    }
}

// ---------------------------------------------------------------------------
extern "C" void kernel_launch(void* const* d_in, const int* in_sizes, int n_in,
                              void* d_out, int out_size)
{
    const float* query = (const float*)d_in[0];
    const float* key   = (const float*)d_in[1];
    const float* value = (const float*)d_in[2];
    const int*   mask  = (const int*)  d_in[3];
    const float* Wq    = (const float*)d_in[4];
    const float* bq    = (const float*)d_in[5];
    const float* Wk    = (const float*)d_in[6];
    const float* bk    = (const float*)d_in[7];
    const float* Wv    = (const float*)d_in[8];
    const float* bv    = (const float*)d_in[9];
    const float* Wo    = (const float*)d_in[10];
    const float* bo    = (const float*)d_in[11];

    float* out = (float*)d_out;
    // Tuple output (out, attn) flattened: attn follows out if the buffer is big enough.
    float* attn_arg = ((long long)out_size >= (long long)OUT_ELEMS + ATTN_ELEMS)
                      ? (out + OUT_ELEMS) : nullptr;

    dim3 blk(256);
    qkv_proj_kernel<<<dim3(4, 32, 3), blk>>>(query, key, value, Wq, bq, Wk, bk, Wv, bv);
    score_kernel  <<<dim3(16, 16, 16), blk>>>(mask, attn_arg);
    softmax_kernel<<<dim3(BATCH*NHEAD*SEQ), blk>>>(attn_arg);
    pv_kernel     <<<dim3(16, 16), blk>>>(attn_arg);
    oproj_kernel  <<<dim3(4, 32), blk>>>(Wo, bo, out);
}

// round 3
// speedup vs baseline: 1.5977x; 1.5977x over previous
#include <cuda_runtime.h>
#include <cuda_bf16.h>
#include <cstdint>
#include <cstddef>

#define D_MODEL 512
#define NHEAD   8
#define DH      64
#define BATCH   2
#define SEQ     2048
#define NTOK    (BATCH*SEQ)   // 4096
#define NBH     (BATCH*NHEAD) // 16

static const int       OUT_ELEMS  = NTOK * D_MODEL;                       // 2,097,152
static const long long ATTN_ELEMS = (long long)BATCH*NHEAD*SEQ*SEQ;       // 67,108,864

// ---------------- device scratch (allocation-free rule) ----------------
__device__ float         g_X[NTOK*D_MODEL];                         // attn@V result (fp32, token-major)
__device__ __nv_bfloat16 g_Qh[NBH*SEQ*DH], g_Ql[NBH*SEQ*DH];        // Q head-sliced [bh][s][d]
__device__ __nv_bfloat16 g_Kh[NBH*SEQ*DH], g_Kl[NBH*SEQ*DH];        // K head-sliced [bh][s][d]
__device__ __nv_bfloat16 g_Vth[NBH*DH*SEQ], g_Vtl[NBH*DH*SEQ];      // V transposed  [bh][d][s]
__device__ __nv_bfloat16 g_Ah[(size_t)NBH*SEQ*SEQ], g_Al[(size_t)NBH*SEQ*SEQ]; // attn hi/lo
__device__ float         g_attn_fallback[(size_t)NBH*SEQ*SEQ];

__device__ __forceinline__ void bf16_split(float v, __nv_bfloat16& hi, __nv_bfloat16& lo) {
    hi = __float2bfloat16(v);
    lo = __float2bfloat16(v - __bfloat162float(hi));
}

// mma.sync m16n8k16 bf16 -> f32 (HMMA path; valid on compute_103)
__device__ __forceinline__ void mma_bf16(float d[4], const uint32_t a[4], const uint32_t b[2]) {
    asm volatile(
        "mma.sync.aligned.m16n8k16.row.col.f32.bf16.bf16.f32 "
        "{%0,%1,%2,%3}, {%4,%5,%6,%7}, {%8,%9}, {%0,%1,%2,%3};\n"
        : "+f"(d[0]), "+f"(d[1]), "+f"(d[2]), "+f"(d[3])
        : "r"(a[0]), "r"(a[1]), "r"(a[2]), "r"(a[3]), "r"(b[0]), "r"(b[1]));
}

// padded smem tile stride (bf16 elements): conflict-free fragment loads
#define TSTRIDE 72
#define TSTRIDE_B (TSTRIDE*2)   // bytes

// ---------------------------------------------------------------------------
// fp32 FFMA SGEMM body (128x128 tile): Y = X @ W^T + bias
// ---------------------------------------------------------------------------
__device__ __forceinline__ void gemm128_acc(
    const float* __restrict__ X, const float* __restrict__ W,
    float acc[8][8], int K, int ldx, int ldw, int m0, int n0)
{
    __shared__ float As[8][128];
    __shared__ float Bs[8][128];
    const int tid  = threadIdx.x;
    const int tx   = tid & 15;
    const int ty   = tid >> 4;
    const int lrow = tid >> 1;
    const int lk4  = (tid & 1) * 4;

#pragma unroll
    for (int i = 0; i < 8; i++)
#pragma unroll
        for (int j = 0; j < 8; j++) acc[i][j] = 0.f;

    for (int k0 = 0; k0 < K; k0 += 8) {
        float4 av = *reinterpret_cast<const float4*>(&X[(size_t)(m0+lrow)*ldx + k0 + lk4]);
        float4 bv = *reinterpret_cast<const float4*>(&W[(size_t)(n0+lrow)*ldw + k0 + lk4]);
        As[lk4+0][lrow]=av.x; As[lk4+1][lrow]=av.y; As[lk4+2][lrow]=av.z; As[lk4+3][lrow]=av.w;
        Bs[lk4+0][lrow]=bv.x; Bs[lk4+1][lrow]=bv.y; Bs[lk4+2][lrow]=bv.z; Bs[lk4+3][lrow]=bv.w;
        __syncthreads();
#pragma unroll
        for (int kk = 0; kk < 8; kk++) {
            float a[8], b[8];
#pragma unroll
            for (int i = 0; i < 8; i++) a[i] = As[kk][ty*8+i];
#pragma unroll
            for (int j = 0; j < 8; j++) b[j] = Bs[kk][tx*8+j];
#pragma unroll
            for (int i = 0; i < 8; i++)
#pragma unroll
                for (int j = 0; j < 8; j++) acc[i][j] = fmaf(a[i], b[j], acc[i][j]);
        }
        __syncthreads();
    }
}

// QKV projections: compute fp32, emit bf16 hi/lo in head-sliced layouts.
__global__ void __launch_bounds__(256)
qkv_proj_kernel(const float* __restrict__ q_in, const float* __restrict__ k_in,
                const float* __restrict__ v_in,
                const float* __restrict__ Wq, const float* __restrict__ bq,
                const float* __restrict__ Wk, const float* __restrict__ bk,
                const float* __restrict__ Wv, const float* __restrict__ bv)
{
    const int zz = blockIdx.z;
    const float* X; const float* W; const float* bias;
    if (zz == 0)      { X = q_in; W = Wq; bias = bq; }
    else if (zz == 1) { X = k_in; W = Wk; bias = bk; }
    else              { X = v_in; W = Wv; bias = bv; }
    const int m0 = blockIdx.y*128, n0 = blockIdx.x*128;

    float acc[8][8];
    gemm128_acc(X, W, acc, D_MODEL, D_MODEL, D_MODEL, m0, n0);

    const int tx = threadIdx.x & 15, ty = threadIdx.x >> 4;
#pragma unroll
    for (int i = 0; i < 8; i++) {
        int token = m0 + ty*8 + i;
        int b = token >> 11, s = token & 2047;
#pragma unroll
        for (int j = 0; j < 8; j++) {
            int col = n0 + tx*8 + j;
            float v = acc[i][j] + bias[col];
            int h = col >> 6, d = col & 63;
            __nv_bfloat16 hi, lo;
            bf16_split(v, hi, lo);
            if (zz == 0) {
                size_t o = ((size_t)(b*NHEAD + h)*SEQ + s)*DH + d;
                g_Qh[o] = hi; g_Ql[o] = lo;
            } else if (zz == 1) {
                size_t o = ((size_t)(b*NHEAD + h)*SEQ + s)*DH + d;
                g_Kh[o] = hi; g_Kl[o] = lo;
            } else {
                size_t o = ((size_t)(b*NHEAD + h)*DH + d)*SEQ + s;
                g_Vth[o] = hi; g_Vtl[o] = lo;
            }
        }
    }
}

// Output projection: out = g_X @ Wo^T + bo (fp32 exact)
__global__ void __launch_bounds__(256)
oproj_kernel(const float* __restrict__ Wo, const float* __restrict__ bo,
             float* __restrict__ out)
{
    const int m0 = blockIdx.y*128, n0 = blockIdx.x*128;
    float acc[8][8];
    gemm128_acc(g_X, Wo, acc, D_MODEL, D_MODEL, D_MODEL, m0, n0);
    const int tx = threadIdx.x & 15, ty = threadIdx.x >> 4;
#pragma unroll
    for (int i = 0; i < 8; i++) {
        int row = m0 + ty*8 + i;
#pragma unroll
        for (int j = 0; j < 8; j++) {
            int col = n0 + tx*8 + j;
            out[(size_t)row*D_MODEL + col] = acc[i][j] + bo[col];
        }
    }
}

// ---------------------------------------------------------------------------
// Score kernel: HMMA bf16 split. 128(i) x 128(j) tile per CTA, K=64.
// 8 warps: warp tile 32(i) x 64(j). smem: Qh,Ql,Kh,Kl 128x64 padded to 72.
// ---------------------------------------------------------------------------
#define TILE_BYTES (128*TSTRIDE_B)               // 18432
#define SCORE_SMEM (4*TILE_BYTES)                // 73728
__global__ void __launch_bounds__(256)
score_kernel(const int* __restrict__ mask, float* attn_arg)
{
    float* attn = attn_arg ? attn_arg : g_attn_fallback;
    extern __shared__ char smem[];
    char* sQ0 = smem;
    char* sQ1 = smem + TILE_BYTES;
    char* sK0 = smem + 2*TILE_BYTES;
    char* sK1 = smem + 3*TILE_BYTES;

    const int tid = threadIdx.x, wid = tid >> 5, lane = tid & 31;
    const int gid = lane >> 2, tig = lane & 3;
    const int bh = blockIdx.z, b = bh >> 3;
    const int m0 = blockIdx.y*128, n0 = blockIdx.x*128;
    const int i0w = (wid & 3) * 32, j0w = (wid >> 2) * 64;

    // load 4 tiles: 128 rows x 64 bf16 each (8 uint4 per row)
    {
        const __nv_bfloat16* srcs[4] = {
            g_Qh + ((size_t)bh*SEQ + m0)*DH, g_Ql + ((size_t)bh*SEQ + m0)*DH,
            g_Kh + ((size_t)bh*SEQ + n0)*DH, g_Kl + ((size_t)bh*SEQ + n0)*DH };
        char* dsts[4] = { sQ0, sQ1, sK0, sK1 };
#pragma unroll
        for (int t = 0; t < 4; t++) {
#pragma unroll
            for (int r = 0; r < 4; r++) {
                int idx = tid + r*256;           // 0..1023
                int row = idx >> 3, c = idx & 7;
                uint4 v = *reinterpret_cast<const uint4*>(srcs[t] + (size_t)row*DH + c*8);
                *reinterpret_cast<uint4*>(dsts[t] + row*TSTRIDE_B + c*16) = v;
            }
        }
    }
    __syncthreads();

    float acc[2][8][4];
#pragma unroll
    for (int mt = 0; mt < 2; mt++)
#pragma unroll
        for (int nt = 0; nt < 8; nt++)
#pragma unroll
            for (int q = 0; q < 4; q++) acc[mt][nt][q] = 0.f;

#pragma unroll
    for (int pass = 0; pass < 3; pass++) {
        const char* A = (pass == 2) ? sQ1 : sQ0;
        const char* B = (pass == 1) ? sK1 : sK0;
#pragma unroll
        for (int ks = 0; ks < 4; ks++) {
            const int kb = (ks*16 + tig*2) * 2;   // byte offset along k
            uint32_t a[2][4];
#pragma unroll
            for (int mt = 0; mt < 2; mt++) {
                const char* base = A + (i0w + mt*16 + gid)*TSTRIDE_B + kb;
                a[mt][0] = *reinterpret_cast<const uint32_t*>(base);
                a[mt][1] = *reinterpret_cast<const uint32_t*>(base + 8*TSTRIDE_B);
                a[mt][2] = *reinterpret_cast<const uint32_t*>(base + 16);
                a[mt][3] = *reinterpret_cast<const uint32_t*>(base + 8*TSTRIDE_B + 16);
            }
#pragma unroll
            for (int nt = 0; nt < 8; nt++) {
                const char* base = B + (j0w + nt*8 + gid)*TSTRIDE_B + kb;
                uint32_t bb[2];
                bb[0] = *reinterpret_cast<const uint32_t*>(base);
                bb[1] = *reinterpret_cast<const uint32_t*>(base + 16);
                mma_bf16(acc[0][nt], a[0], bb);
                mma_bf16(acc[1][nt], a[1], bb);
            }
        }
    }

    // epilogue: scale, mask, store fp32 attn
#pragma unroll
    for (int nt = 0; nt < 8; nt++) {
        const int col = n0 + j0w + nt*8 + tig*2;
        const int mv0 = __ldg(mask + b*SEQ + col);
        const int mv1 = __ldg(mask + b*SEQ + col + 1);
#pragma unroll
        for (int mt = 0; mt < 2; mt++) {
#pragma unroll
            for (int half = 0; half < 2; half++) {
                const int row = m0 + i0w + mt*16 + gid + half*8;
                float v0 = acc[mt][nt][half*2+0] * 0.125f;
                float v1 = acc[mt][nt][half*2+1] * 0.125f;
                if (mv0 == 0) v0 = -1.0e9f;
                if (mv1 == 0) v1 = -1.0e9f;
                float2 o; o.x = v0; o.y = v1;
                *reinterpret_cast<float2*>(attn + ((size_t)bh*SEQ + row)*SEQ + col) = o;
            }
        }
    }
}

// ---------------------------------------------------------------------------
// Softmax: per-row (2048), normalize in place, emit bf16 hi/lo of attn.
// ---------------------------------------------------------------------------
__global__ void __launch_bounds__(256)
softmax_kernel(float* attn_arg)
{
    float* attn = attn_arg ? attn_arg : g_attn_fallback;
    __shared__ float red[8];
    const size_t row = blockIdx.x;
    float* p = attn + row * (size_t)SEQ;
    const int tid = threadIdx.x;

    float4 v0 = reinterpret_cast<float4*>(p)[2*tid + 0];
    float4 v1 = reinterpret_cast<float4*>(p)[2*tid + 1];

    float m = fmaxf(fmaxf(fmaxf(v0.x,v0.y), fmaxf(v0.z,v0.w)),
                    fmaxf(fmaxf(v1.x,v1.y), fmaxf(v1.z,v1.w)));
#pragma unroll
    for (int o = 16; o; o >>= 1) m = fmaxf(m, __shfl_xor_sync(0xffffffffu, m, o));
    if ((tid & 31) == 0) red[tid >> 5] = m;
    __syncthreads();
    m = red[0];
#pragma unroll
    for (int w = 1; w < 8; w++) m = fmaxf(m, red[w]);
    __syncthreads();

    v0.x = expf(v0.x - m); v0.y = expf(v0.y - m); v0.z = expf(v0.z - m); v0.w = expf(v0.w - m);
    v1.x = expf(v1.x - m); v1.y = expf(v1.y - m); v1.z = expf(v1.z - m); v1.w = expf(v1.w - m);

    float s = v0.x + v0.y + v0.z + v0.w + v1.x + v1.y + v1.z + v1.w;
#pragma unroll
    for (int o = 16; o; o >>= 1) s += __shfl_xor_sync(0xffffffffu, s, o);
    if ((tid & 31) == 0) red[tid >> 5] = s;
    __syncthreads();
    s = red[0];
#pragma unroll
    for (int w = 1; w < 8; w++) s += red[w];

    const float inv = 1.0f / s;
    v0.x *= inv; v0.y *= inv; v0.z *= inv; v0.w *= inv;
    v1.x *= inv; v1.y *= inv; v1.z *= inv; v1.w *= inv;
    reinterpret_cast<float4*>(p)[2*tid + 0] = v0;
    reinterpret_cast<float4*>(p)[2*tid + 1] = v1;

    float vf[8] = { v0.x, v0.y, v0.z, v0.w, v1.x, v1.y, v1.z, v1.w };
    __nv_bfloat16 hb[8], lb[8];
#pragma unroll
    for (int e = 0; e < 8; e++) bf16_split(vf[e], hb[e], lb[e]);
    size_t off = row * (size_t)SEQ + tid*8;
    *reinterpret_cast<uint4*>(g_Ah + off) = *reinterpret_cast<uint4*>(hb);
    *reinterpret_cast<uint4*>(g_Al + off) = *reinterpret_cast<uint4*>(lb);
}

// ---------------------------------------------------------------------------
// PV kernel: HMMA bf16 split. 128(i) x 64(d) per CTA, K=2048 in 32 chunks.
// 8 warps: warp tile 32(i) x 32(d). Register-staged global prefetch.
// smem: Ah,Al 128x64 (18432B each), Bh,Bl 64x64 (9216B each) padded to 72.
// ---------------------------------------------------------------------------
#define PV_BTILE (64*TSTRIDE_B)                  // 9216
#define PV_SMEM  (2*TILE_BYTES + 2*PV_BTILE)     // 55296
__global__ void __launch_bounds__(256)
pv_kernel()
{
    extern __shared__ char smem[];
    char* sA0 = smem;
    char* sA1 = smem + TILE_BYTES;
    char* sB0 = smem + 2*TILE_BYTES;
    char* sB1 = smem + 2*TILE_BYTES + PV_BTILE;

    const int tid = threadIdx.x, wid = tid >> 5, lane = tid & 31;
    const int gid = lane >> 2, tig = lane & 3;
    const int bh = blockIdx.y, b = bh >> 3, h = bh & 7;
    const int m0 = blockIdx.x * 128;
    const int i0w = (wid & 3) * 32, d0w = (wid >> 2) * 32;

    const __nv_bfloat16* Ah = g_Ah + ((size_t)bh*SEQ + m0)*SEQ;
    const __nv_bfloat16* Al = g_Al + ((size_t)bh*SEQ + m0)*SEQ;
    const __nv_bfloat16* Bh = g_Vth + (size_t)bh*DH*SEQ;
    const __nv_bfloat16* Bl = g_Vtl + (size_t)bh*DH*SEQ;

    // per-thread staging: A 4+4 uint4, B 2+2 uint4
    const int arow = tid >> 3, ac = tid & 7;      // + t*32 rows
    uint4 stA0[4], stA1[4], stB0[2], stB1[2];

    {
        const int j0 = 0;
#pragma unroll
        for (int t = 0; t < 4; t++) {
            stA0[t] = *reinterpret_cast<const uint4*>(Ah + (size_t)(arow + t*32)*SEQ + j0 + ac*8);
            stA1[t] = *reinterpret_cast<const uint4*>(Al + (size_t)(arow + t*32)*SEQ + j0 + ac*8);
        }
#pragma unroll
        for (int t = 0; t < 2; t++) {
            stB0[t] = *reinterpret_cast<const uint4*>(Bh + (size_t)(arow + t*32)*SEQ + j0 + ac*8);
            stB1[t] = *reinterpret_cast<const uint4*>(Bl + (size_t)(arow + t*32)*SEQ + j0 + ac*8);
        }
    }

    float acc[2][4][4];
#pragma unroll
    for (int mt = 0; mt < 2; mt++)
#pragma unroll
        for (int nt = 0; nt < 4; nt++)
#pragma unroll
            for (int q = 0; q < 4; q++) acc[mt][nt][q] = 0.f;

    for (int ch = 0; ch < 32; ch++) {
        __syncthreads();
        // commit staged regs to smem
#pragma unroll
        for (int t = 0; t < 4; t++) {
            *reinterpret_cast<uint4*>(sA0 + (arow + t*32)*TSTRIDE_B + ac*16) = stA0[t];
            *reinterpret_cast<uint4*>(sA1 + (arow + t*32)*TSTRIDE_B + ac*16) = stA1[t];
        }
#pragma unroll
        for (int t = 0; t < 2; t++) {
            *reinterpret_cast<uint4*>(sB0 + (arow + t*32)*TSTRIDE_B + ac*16) = stB0[t];
            *reinterpret_cast<uint4*>(sB1 + (arow + t*32)*TSTRIDE_B + ac*16) = stB1[t];
        }
        __syncthreads();

        // prefetch next chunk
        if (ch < 31) {
            const int j0 = (ch + 1) * 64;
#pragma unroll
            for (int t = 0; t < 4; t++) {
                stA0[t] = *reinterpret_cast<const uint4*>(Ah + (size_t)(arow + t*32)*SEQ + j0 + ac*8);
                stA1[t] = *reinterpret_cast<const uint4*>(Al + (size_t)(arow + t*32)*SEQ + j0 + ac*8);
            }
#pragma unroll
            for (int t = 0; t < 2; t++) {
                stB0[t] = *reinterpret_cast<const uint4*>(Bh + (size_t)(arow + t*32)*SEQ + j0 + ac*8);
                stB1[t] = *reinterpret_cast<const uint4*>(Bl + (size_t)(arow + t*32)*SEQ + j0 + ac*8);
            }
        }

        // compute this chunk: 3 passes x 4 ksteps
#pragma unroll
        for (int pass = 0; pass < 3; pass++) {
            const char* A = (pass == 2) ? sA1 : sA0;
            const char* B = (pass == 1) ? sB1 : sB0;
#pragma unroll
            for (int ks = 0; ks < 4; ks++) {
                const int kb = (ks*16 + tig*2) * 2;
                uint32_t a[2][4];
#pragma unroll
                for (int mt = 0; mt < 2; mt++) {
                    const char* base = A + (i0w + mt*16 + gid)*TSTRIDE_B + kb;
                    a[mt][0] = *reinterpret_cast<const uint32_t*>(base);
                    a[mt][1] = *reinterpret_cast<const uint32_t*>(base + 8*TSTRIDE_B);
                    a[mt][2] = *reinterpret_cast<const uint32_t*>(base + 16);
                    a[mt][3] = *reinterpret_cast<const uint32_t*>(base + 8*TSTRIDE_B + 16);
                }
#pragma unroll
                for (int nt = 0; nt < 4; nt++) {
                    const char* base = B + (d0w + nt*8 + gid)*TSTRIDE_B + kb;
                    uint32_t bb[2];
                    bb[0] = *reinterpret_cast<const uint32_t*>(base);
                    bb[1] = *reinterpret_cast<const uint32_t*>(base + 16);
                    mma_bf16(acc[0][nt], a[0], bb);
                    mma_bf16(acc[1][nt], a[1], bb);
                }
            }
        }
    }

    // epilogue: write g_X fp32
#pragma unroll
    for (int nt = 0; nt < 4; nt++) {
        const int d = d0w + nt*8 + tig*2;
#pragma unroll
        for (int mt = 0; mt < 2; mt++) {
#pragma unroll
            for (int half = 0; half < 2; half++) {
                const int row = m0 + i0w + mt*16 + gid + half*8;
                float2 o;
                o.x = acc[mt][nt][half*2+0];
                o.y = acc[mt][nt][half*2+1];
                *reinterpret_cast<float2*>(g_X + ((size_t)(b*SEQ + row))*D_MODEL + h*DH + d) = o;
            }
        }
    }
}

// ---------------------------------------------------------------------------
extern "C" void kernel_launch(void* const* d_in, const int* in_sizes, int n_in,
                              void* d_out, int out_size)
{
    const float* query = (const float*)d_in[0];
    const float* key   = (const float*)d_in[1];
    const float* value = (const float*)d_in[2];
    const int*   mask  = (const int*)  d_in[3];
    const float* Wq    = (const float*)d_in[4];
    const float* bq    = (const float*)d_in[5];
    const float* Wk    = (const float*)d_in[6];
    const float* bk    = (const float*)d_in[7];
    const float* Wv    = (const float*)d_in[8];
    const float* bv    = (const float*)d_in[9];
    const float* Wo    = (const float*)d_in[10];
    const float* bo    = (const float*)d_in[11];

    float* out = (float*)d_out;
    float* attn_arg = ((long long)out_size >= (long long)OUT_ELEMS + ATTN_ELEMS)
                      ? (out + OUT_ELEMS) : nullptr;

    static bool attr_done = false;
    if (!attr_done) {
        cudaFuncSetAttribute(score_kernel, cudaFuncAttributeMaxDynamicSharedMemorySize, SCORE_SMEM);
        cudaFuncSetAttribute(pv_kernel,    cudaFuncAttributeMaxDynamicSharedMemorySize, PV_SMEM);
        attr_done = true;
    }

    dim3 blk(256);
    qkv_proj_kernel<<<dim3(4, 32, 3), blk>>>(query, key, value, Wq, bq, Wk, bk, Wv, bv);
    score_kernel  <<<dim3(16, 16, 16), blk, SCORE_SMEM>>>(mask, attn_arg);
    softmax_kernel<<<dim3(NBH*SEQ), blk>>>(attn_arg);
    pv_kernel     <<<dim3(16, 16), blk, PV_SMEM>>>();
    oproj_kernel  <<<dim3(4, 32), blk>>>(Wo, bo, out);
}

// round 4
// speedup vs baseline: 2.4007x; 1.5026x over previous
#include <cuda_runtime.h>
#include <cuda_bf16.h>
#include <cstdint>
#include <cstddef>

#define D_MODEL 512
#define NHEAD   8
#define DH      64
#define BATCH   2
#define SEQ     2048
#define NTOK    (BATCH*SEQ)   // 4096
#define NBH     (BATCH*NHEAD) // 16
#define N1      (NTOK*D_MODEL)     // 2,097,152
#define N2      (D_MODEL*D_MODEL)  // 262,144

static const int       OUT_ELEMS  = N1;
static const long long ATTN_ELEMS = (long long)NBH*SEQ*SEQ;

// ---------------- device scratch (allocation-free rule) ----------------
__device__ __align__(16) __nv_bfloat16 g_INh[3*N1], g_INl[3*N1];     // split q,k,v inputs
__device__ __align__(16) __nv_bfloat16 g_Wh[4*N2],  g_Wl[4*N2];      // split Wq,Wk,Wv,Wo
__device__ __align__(16) __nv_bfloat16 g_Qh[NBH*SEQ*DH], g_Ql[NBH*SEQ*DH];
__device__ __align__(16) __nv_bfloat16 g_Kh[NBH*SEQ*DH], g_Kl[NBH*SEQ*DH];
__device__ __align__(16) __nv_bfloat16 g_Vth[NBH*DH*SEQ], g_Vtl[NBH*DH*SEQ]; // V transposed [bh][d][s]
__device__ __align__(16) __nv_bfloat16 g_Ah[(size_t)NBH*SEQ*SEQ], g_Al[(size_t)NBH*SEQ*SEQ];
__device__ __align__(16) __nv_bfloat16 g_Xh[N1], g_Xl[N1];           // attn@V result hi/lo
__device__ __align__(16) float         g_attn_fallback[(size_t)NBH*SEQ*SEQ];

// ---------------- helpers ----------------
__device__ __forceinline__ uint32_t smem_u32(const void* p) {
    uint32_t a;
    asm("{ .reg .u64 t; cvta.to.shared.u64 t, %1; cvt.u32.u64 %0, t; }" : "=r"(a) : "l"(p));
    return a;
}
__device__ __forceinline__ void bf16_split(float v, __nv_bfloat16& hi, __nv_bfloat16& lo) {
    hi = __float2bfloat16(v);
    lo = __float2bfloat16(v - __bfloat162float(hi));
}
__device__ __forceinline__ uint32_t pack2(__nv_bfloat16 a, __nv_bfloat16 b) {
    return (uint32_t)__bfloat16_as_ushort(a) | ((uint32_t)__bfloat16_as_ushort(b) << 16);
}
__device__ __forceinline__ void mma_bf16(float d[4], const uint32_t a[4], const uint32_t b[2]) {
    asm volatile(
        "mma.sync.aligned.m16n8k16.row.col.f32.bf16.bf16.f32 "
        "{%0,%1,%2,%3}, {%4,%5,%6,%7}, {%8,%9}, {%0,%1,%2,%3};\n"
        : "+f"(d[0]), "+f"(d[1]), "+f"(d[2]), "+f"(d[3])
        : "r"(a[0]), "r"(a[1]), "r"(a[2]), "r"(a[3]), "r"(b[0]), "r"(b[1]));
}

#define TSTRIDE_B 144                 // 72 bf16, conflict-free padded stride
#define TILE_BYTES (128*TSTRIDE_B)    // 18432 (128 rows x 64 bf16)
#define BTILE64    (64*TSTRIDE_B)     // 9216  (64 rows x 64 bf16)

#define CP_COMMIT() asm volatile("cp.async.commit_group;" ::: "memory")

// cp.async a 128x64 bf16 tile (row-major src, ld elements) into padded smem
__device__ __forceinline__ void cp_tile128(char* dst, const __nv_bfloat16* src, int ld, int tid) {
    const int row = tid >> 3, c = tid & 7;
#pragma unroll
    for (int t = 0; t < 4; t++) {
        uint32_t d = smem_u32(dst + (row + t*32)*TSTRIDE_B + c*16);
        const void* g = src + (size_t)(row + t*32)*ld + c*8;
        asm volatile("cp.async.cg.shared.global [%0], [%1], 16;" :: "r"(d), "l"(g) : "memory");
    }
}
__device__ __forceinline__ void cp_tile64(char* dst, const __nv_bfloat16* src, int ld, int tid) {
    const int row = tid >> 3, c = tid & 7;
#pragma unroll
    for (int t = 0; t < 2; t++) {
        uint32_t d = smem_u32(dst + (row + t*32)*TSTRIDE_B + c*16);
        const void* g = src + (size_t)(row + t*32)*ld + c*8;
        asm volatile("cp.async.cg.shared.global [%0], [%1], 16;" :: "r"(d), "l"(g) : "memory");
    }
}

// 3-pass (hh + h*lo + lo*h) HMMA over one 64-deep K chunk.
// Warp tile: 32(i) x NT*8(j). A tiles 128 rows; B tiles NT*8*? rows at j0w base.
template<int NT>
__device__ __forceinline__ void hmma_3pass(
    const char* A0, const char* A1, const char* B0, const char* B1,
    int i0w, int j0w, int gid, int tig, float acc[2][NT][4])
{
#pragma unroll
    for (int pass = 0; pass < 3; pass++) {
        const char* A = (pass == 2) ? A1 : A0;
        const char* B = (pass == 1) ? B1 : B0;
#pragma unroll
        for (int ks = 0; ks < 4; ks++) {
            const int kb = (ks*16 + tig*2) * 2;
            uint32_t a[2][4];
#pragma unroll
            for (int mt = 0; mt < 2; mt++) {
                const char* base = A + (i0w + mt*16 + gid)*TSTRIDE_B + kb;
                a[mt][0] = *reinterpret_cast<const uint32_t*>(base);
                a[mt][1] = *reinterpret_cast<const uint32_t*>(base + 8*TSTRIDE_B);
                a[mt][2] = *reinterpret_cast<const uint32_t*>(base + 16);
                a[mt][3] = *reinterpret_cast<const uint32_t*>(base + 8*TSTRIDE_B + 16);
            }
#pragma unroll
            for (int nt = 0; nt < NT; nt++) {
                const char* base = B + (j0w + nt*8 + gid)*TSTRIDE_B + kb;
                uint32_t bb[2];
                bb[0] = *reinterpret_cast<const uint32_t*>(base);
                bb[1] = *reinterpret_cast<const uint32_t*>(base + 16);
                mma_bf16(acc[0][nt], a[0], bb);
                mma_bf16(acc[1][nt], a[1], bb);
            }
        }
    }
}

// ---------------------------------------------------------------------------
// Split kernel: fp32 -> bf16 hi/lo for 3 inputs + 4 weight matrices
// ---------------------------------------------------------------------------
__global__ void __launch_bounds__(256)
split_kernel(const float* __restrict__ q, const float* __restrict__ k, const float* __restrict__ v,
             const float* __restrict__ Wq, const float* __restrict__ Wk,
             const float* __restrict__ Wv, const float* __restrict__ Wo)
{
    const int which = blockIdx.y;
    const float* src; __nv_bfloat16* dh; __nv_bfloat16* dl; int count;
    if (which < 3) {
        src = (which == 0) ? q : (which == 1) ? k : v;
        dh = g_INh + (size_t)which*N1; dl = g_INl + (size_t)which*N1; count = N1/4;
    } else {
        const int w = which - 3;
        src = (w == 0) ? Wq : (w == 1) ? Wk : (w == 2) ? Wv : Wo;
        dh = g_Wh + (size_t)w*N2; dl = g_Wl + (size_t)w*N2; count = N2/4;
    }
    for (int i = blockIdx.x*blockDim.x + threadIdx.x; i < count; i += gridDim.x*blockDim.x) {
        float4 x = reinterpret_cast<const float4*>(src)[i];
        __nv_bfloat16 h0,l0,h1,l1,h2,l2,h3,l3;
        bf16_split(x.x,h0,l0); bf16_split(x.y,h1,l1);
        bf16_split(x.z,h2,l2); bf16_split(x.w,h3,l3);
        uint2 ph, pl;
        ph.x = pack2(h0,h1); ph.y = pack2(h2,h3);
        pl.x = pack2(l0,l1); pl.y = pack2(l2,l3);
        reinterpret_cast<uint2*>(dh)[i] = ph;
        reinterpret_cast<uint2*>(dl)[i] = pl;
    }
}

// ---------------------------------------------------------------------------
// QKV projection: HMMA split, 128x128 tile, K=512 (8 chunks), cp.async 2-deep.
// Epilogue: +bias, split to bf16 hi/lo, write head-sliced (V transposed).
// ---------------------------------------------------------------------------
#define PROJ_SMEM (8*TILE_BYTES)   // 147456
__global__ void __launch_bounds__(256)
qkv_proj_kernel(const float* __restrict__ bq, const float* __restrict__ bk,
                const float* __restrict__ bv)
{
    extern __shared__ char smem[];
    const int tid = threadIdx.x, wid = tid >> 5, lane = tid & 31;
    const int gid = lane >> 2, tig = lane & 3;
    const int z = blockIdx.z;
    const int m0 = blockIdx.y*128, n0 = blockIdx.x*128;
    const int i0w = (wid & 3)*32, j0w = (wid >> 2)*64;

    const __nv_bfloat16* Ah = g_INh + (size_t)z*N1 + (size_t)m0*D_MODEL;
    const __nv_bfloat16* Al = g_INl + (size_t)z*N1 + (size_t)m0*D_MODEL;
    const __nv_bfloat16* Bh = g_Wh  + (size_t)z*N2 + (size_t)n0*D_MODEL;
    const __nv_bfloat16* Bl = g_Wl  + (size_t)z*N2 + (size_t)n0*D_MODEL;
    const float* bias = (z == 0) ? bq : (z == 1) ? bk : bv;

    float acc[2][8][4];
#pragma unroll
    for (int mt = 0; mt < 2; mt++)
#pragma unroll
        for (int nt = 0; nt < 8; nt++)
#pragma unroll
            for (int q = 0; q < 4; q++) acc[mt][nt][q] = 0.f;

    // chunk 0 issue
    {
        char* buf = smem;
        cp_tile128(buf,               Ah, D_MODEL, tid);
        cp_tile128(buf +   TILE_BYTES, Al, D_MODEL, tid);
        cp_tile128(buf + 2*TILE_BYTES, Bh, D_MODEL, tid);
        cp_tile128(buf + 3*TILE_BYTES, Bl, D_MODEL, tid);
        CP_COMMIT();
    }
    for (int ch = 0; ch < 8; ch++) {
        if (ch < 7) {
            char* buf = smem + ((ch+1)&1)*(4*TILE_BYTES);
            const int k0 = (ch+1)*64;
            cp_tile128(buf,               Ah + k0, D_MODEL, tid);
            cp_tile128(buf +   TILE_BYTES, Al + k0, D_MODEL, tid);
            cp_tile128(buf + 2*TILE_BYTES, Bh + k0, D_MODEL, tid);
            cp_tile128(buf + 3*TILE_BYTES, Bl + k0, D_MODEL, tid);
            CP_COMMIT();
            asm volatile("cp.async.wait_group 1;" ::: "memory");
        } else {
            asm volatile("cp.async.wait_group 0;" ::: "memory");
        }
        __syncthreads();
        char* buf = smem + (ch&1)*(4*TILE_BYTES);
        hmma_3pass<8>(buf, buf + TILE_BYTES, buf + 2*TILE_BYTES, buf + 3*TILE_BYTES,
                      i0w, j0w, gid, tig, acc);
        __syncthreads();
    }

    // epilogue
#pragma unroll
    for (int nt = 0; nt < 8; nt++) {
        const int col = n0 + j0w + nt*8 + tig*2;
        const int h = col >> 6, d = col & 63;
        const float b0v = bias[col], b1v = bias[col+1];
#pragma unroll
        for (int mt = 0; mt < 2; mt++) {
#pragma unroll
            for (int half = 0; half < 2; half++) {
                const int token = m0 + i0w + mt*16 + gid + half*8;
                const int b = token >> 11, s = token & 2047;
                float v0 = acc[mt][nt][half*2+0] + b0v;
                float v1 = acc[mt][nt][half*2+1] + b1v;
                __nv_bfloat16 h0,l0,h1,l1;
                bf16_split(v0,h0,l0); bf16_split(v1,h1,l1);
                if (z == 0) {
                    size_t o = ((size_t)(b*NHEAD + h)*SEQ + s)*DH + d;
                    *reinterpret_cast<uint32_t*>(g_Qh + o) = pack2(h0,h1);
                    *reinterpret_cast<uint32_t*>(g_Ql + o) = pack2(l0,l1);
                } else if (z == 1) {
                    size_t o = ((size_t)(b*NHEAD + h)*SEQ + s)*DH + d;
                    *reinterpret_cast<uint32_t*>(g_Kh + o) = pack2(h0,h1);
                    *reinterpret_cast<uint32_t*>(g_Kl + o) = pack2(l0,l1);
                } else {
                    size_t o0 = ((size_t)(b*NHEAD + h)*DH + d)*SEQ + s;
                    g_Vth[o0] = h0; g_Vtl[o0] = l0;
                    g_Vth[o0 + SEQ] = h1; g_Vtl[o0 + SEQ] = l1;
                }
            }
        }
    }
}

// ---------------------------------------------------------------------------
// Output projection: HMMA split, A = g_Xh/g_Xl, B = Wo hi/lo, out fp32 + bias.
// ---------------------------------------------------------------------------
__global__ void __launch_bounds__(256)
oproj_kernel(const float* __restrict__ bo, float* __restrict__ out)
{
    extern __shared__ char smem[];
    const int tid = threadIdx.x, wid = tid >> 5, lane = tid & 31;
    const int gid = lane >> 2, tig = lane & 3;
    const int m0 = blockIdx.y*128, n0 = blockIdx.x*128;
    const int i0w = (wid & 3)*32, j0w = (wid >> 2)*64;

    const __nv_bfloat16* Ah = g_Xh + (size_t)m0*D_MODEL;
    const __nv_bfloat16* Al = g_Xl + (size_t)m0*D_MODEL;
    const __nv_bfloat16* Bh = g_Wh + (size_t)3*N2 + (size_t)n0*D_MODEL;
    const __nv_bfloat16* Bl = g_Wl + (size_t)3*N2 + (size_t)n0*D_MODEL;

    float acc[2][8][4];
#pragma unroll
    for (int mt = 0; mt < 2; mt++)
#pragma unroll
        for (int nt = 0; nt < 8; nt++)
#pragma unroll
            for (int q = 0; q < 4; q++) acc[mt][nt][q] = 0.f;

    {
        char* buf = smem;
        cp_tile128(buf,               Ah, D_MODEL, tid);
        cp_tile128(buf +   TILE_BYTES, Al, D_MODEL, tid);
        cp_tile128(buf + 2*TILE_BYTES, Bh, D_MODEL, tid);
        cp_tile128(buf + 3*TILE_BYTES, Bl, D_MODEL, tid);
        CP_COMMIT();
    }
    for (int ch = 0; ch < 8; ch++) {
        if (ch < 7) {
            char* buf = smem + ((ch+1)&1)*(4*TILE_BYTES);
            const int k0 = (ch+1)*64;
            cp_tile128(buf,               Ah + k0, D_MODEL, tid);
            cp_tile128(buf +   TILE_BYTES, Al + k0, D_MODEL, tid);
            cp_tile128(buf + 2*TILE_BYTES, Bh + k0, D_MODEL, tid);
            cp_tile128(buf + 3*TILE_BYTES, Bl + k0, D_MODEL, tid);
            CP_COMMIT();
            asm volatile("cp.async.wait_group 1;" ::: "memory");
        } else {
            asm volatile("cp.async.wait_group 0;" ::: "memory");
        }
        __syncthreads();
        char* buf = smem + (ch&1)*(4*TILE_BYTES);
        hmma_3pass<8>(buf, buf + TILE_BYTES, buf + 2*TILE_BYTES, buf + 3*TILE_BYTES,
                      i0w, j0w, gid, tig, acc);
        __syncthreads();
    }

#pragma unroll
    for (int nt = 0; nt < 8; nt++) {
        const int col = n0 + j0w + nt*8 + tig*2;
        const float b0v = bo[col], b1v = bo[col+1];
#pragma unroll
        for (int mt = 0; mt < 2; mt++) {
#pragma unroll
            for (int half = 0; half < 2; half++) {
                const int row = m0 + i0w + mt*16 + gid + half*8;
                float2 o;
                o.x = acc[mt][nt][half*2+0] + b0v;
                o.y = acc[mt][nt][half*2+1] + b1v;
                *reinterpret_cast<float2*>(out + (size_t)row*D_MODEL + col) = o;
            }
        }
    }
}

// ---------------------------------------------------------------------------
// Score kernel: unchanged from R3 (single K=64 chunk). 128x128 tile.
// ---------------------------------------------------------------------------
#define SCORE_SMEM (4*TILE_BYTES)
__global__ void __launch_bounds__(256)
score_kernel(const int* __restrict__ mask, float* attn_arg)
{
    float* attn = attn_arg ? attn_arg : g_attn_fallback;
    extern __shared__ char smem[];
    char* sQ0 = smem;
    char* sQ1 = smem + TILE_BYTES;
    char* sK0 = smem + 2*TILE_BYTES;
    char* sK1 = smem + 3*TILE_BYTES;

    const int tid = threadIdx.x, wid = tid >> 5, lane = tid & 31;
    const int gid = lane >> 2, tig = lane & 3;
    const int bh = blockIdx.z, b = bh >> 3;
    const int m0 = blockIdx.y*128, n0 = blockIdx.x*128;
    const int i0w = (wid & 3)*32, j0w = (wid >> 2)*64;

    cp_tile128(sQ0, g_Qh + ((size_t)bh*SEQ + m0)*DH, DH, tid);
    cp_tile128(sQ1, g_Ql + ((size_t)bh*SEQ + m0)*DH, DH, tid);
    cp_tile128(sK0, g_Kh + ((size_t)bh*SEQ + n0)*DH, DH, tid);
    cp_tile128(sK1, g_Kl + ((size_t)bh*SEQ + n0)*DH, DH, tid);
    CP_COMMIT();
    asm volatile("cp.async.wait_group 0;" ::: "memory");
    __syncthreads();

    float acc[2][8][4];
#pragma unroll
    for (int mt = 0; mt < 2; mt++)
#pragma unroll
        for (int nt = 0; nt < 8; nt++)
#pragma unroll
            for (int q = 0; q < 4; q++) acc[mt][nt][q] = 0.f;

    hmma_3pass<8>(sQ0, sQ1, sK0, sK1, i0w, j0w, gid, tig, acc);

#pragma unroll
    for (int nt = 0; nt < 8; nt++) {
        const int col = n0 + j0w + nt*8 + tig*2;
        const int mv0 = __ldg(mask + b*SEQ + col);
        const int mv1 = __ldg(mask + b*SEQ + col + 1);
#pragma unroll
        for (int mt = 0; mt < 2; mt++) {
#pragma unroll
            for (int half = 0; half < 2; half++) {
                const int row = m0 + i0w + mt*16 + gid + half*8;
                float v0 = acc[mt][nt][half*2+0] * 0.125f;
                float v1 = acc[mt][nt][half*2+1] * 0.125f;
                if (mv0 == 0) v0 = -1.0e9f;
                if (mv1 == 0) v1 = -1.0e9f;
                float2 o; o.x = v0; o.y = v1;
                *reinterpret_cast<float2*>(attn + ((size_t)bh*SEQ + row)*SEQ + col) = o;
            }
        }
    }
}

// ---------------------------------------------------------------------------
// Softmax: per-row, normalize in place, emit bf16 hi/lo.
// ---------------------------------------------------------------------------
__global__ void __launch_bounds__(256)
softmax_kernel(float* attn_arg)
{
    float* attn = attn_arg ? attn_arg : g_attn_fallback;
    __shared__ float red[8];
    const size_t row = blockIdx.x;
    float* p = attn + row * (size_t)SEQ;
    const int tid = threadIdx.x;

    float4 v0 = reinterpret_cast<float4*>(p)[2*tid + 0];
    float4 v1 = reinterpret_cast<float4*>(p)[2*tid + 1];

    float m = fmaxf(fmaxf(fmaxf(v0.x,v0.y), fmaxf(v0.z,v0.w)),
                    fmaxf(fmaxf(v1.x,v1.y), fmaxf(v1.z,v1.w)));
#pragma unroll
    for (int o = 16; o; o >>= 1) m = fmaxf(m, __shfl_xor_sync(0xffffffffu, m, o));
    if ((tid & 31) == 0) red[tid >> 5] = m;
    __syncthreads();
    m = red[0];
#pragma unroll
    for (int w = 1; w < 8; w++) m = fmaxf(m, red[w]);
    __syncthreads();

    v0.x = expf(v0.x - m); v0.y = expf(v0.y - m); v0.z = expf(v0.z - m); v0.w = expf(v0.w - m);
    v1.x = expf(v1.x - m); v1.y = expf(v1.y - m); v1.z = expf(v1.z - m); v1.w = expf(v1.w - m);

    float s = v0.x + v0.y + v0.z + v0.w + v1.x + v1.y + v1.z + v1.w;
#pragma unroll
    for (int o = 16; o; o >>= 1) s += __shfl_xor_sync(0xffffffffu, s, o);
    if ((tid & 31) == 0) red[tid >> 5] = s;
    __syncthreads();
    s = red[0];
#pragma unroll
    for (int w = 1; w < 8; w++) s += red[w];

    const float inv = 1.0f / s;
    v0.x *= inv; v0.y *= inv; v0.z *= inv; v0.w *= inv;
    v1.x *= inv; v1.y *= inv; v1.z *= inv; v1.w *= inv;
    reinterpret_cast<float4*>(p)[2*tid + 0] = v0;
    reinterpret_cast<float4*>(p)[2*tid + 1] = v1;

    float vf[8] = { v0.x, v0.y, v0.z, v0.w, v1.x, v1.y, v1.z, v1.w };
    __nv_bfloat16 hb[8], lb[8];
#pragma unroll
    for (int e = 0; e < 8; e++) bf16_split(vf[e], hb[e], lb[e]);
    size_t off = row * (size_t)SEQ + tid*8;
    *reinterpret_cast<uint4*>(g_Ah + off) = *reinterpret_cast<uint4*>(hb);
    *reinterpret_cast<uint4*>(g_Al + off) = *reinterpret_cast<uint4*>(lb);
}

// ---------------------------------------------------------------------------
// PV kernel: 128(i) x 64(d), K=2048 in 32 chunks, cp.async 2-deep.
// Epilogue: split to bf16 hi/lo for oproj.
// ---------------------------------------------------------------------------
#define PVBUF   (2*TILE_BYTES + 2*BTILE64)   // 55296
#define PV_SMEM (2*PVBUF)                     // 110592
__global__ void __launch_bounds__(256)
pv_kernel()
{
    extern __shared__ char smem[];
    const int tid = threadIdx.x, wid = tid >> 5, lane = tid & 31;
    const int gid = lane >> 2, tig = lane & 3;
    const int bh = blockIdx.y, b = bh >> 3, h = bh & 7;
    const int m0 = blockIdx.x * 128;
    const int i0w = (wid & 3)*32, d0w = (wid >> 2)*32;

    const __nv_bfloat16* Ah = g_Ah + ((size_t)bh*SEQ + m0)*SEQ;
    const __nv_bfloat16* Al = g_Al + ((size_t)bh*SEQ + m0)*SEQ;
    const __nv_bfloat16* Bh = g_Vth + (size_t)bh*DH*SEQ;
    const __nv_bfloat16* Bl = g_Vtl + (size_t)bh*DH*SEQ;

    float acc[2][4][4];
#pragma unroll
    for (int mt = 0; mt < 2; mt++)
#pragma unroll
        for (int nt = 0; nt < 4; nt++)
#pragma unroll
            for (int q = 0; q < 4; q++) acc[mt][nt][q] = 0.f;

    {
        char* buf = smem;
        cp_tile128(buf,                        Ah, SEQ, tid);
        cp_tile128(buf + TILE_BYTES,           Al, SEQ, tid);
        cp_tile64 (buf + 2*TILE_BYTES,          Bh, SEQ, tid);
        cp_tile64 (buf + 2*TILE_BYTES + BTILE64, Bl, SEQ, tid);
        CP_COMMIT();
    }
    for (int ch = 0; ch < 32; ch++) {
        if (ch < 31) {
            char* buf = smem + ((ch+1)&1)*PVBUF;
            const int j0 = (ch+1)*64;
            cp_tile128(buf,                        Ah + j0, SEQ, tid);
            cp_tile128(buf + TILE_BYTES,           Al + j0, SEQ, tid);
            cp_tile64 (buf + 2*TILE_BYTES,          Bh + j0, SEQ, tid);
            cp_tile64 (buf + 2*TILE_BYTES + BTILE64, Bl + j0, SEQ, tid);
            CP_COMMIT();
            asm volatile("cp.async.wait_group 1;" ::: "memory");
        } else {
            asm volatile("cp.async.wait_group 0;" ::: "memory");
        }
        __syncthreads();
        char* buf = smem + (ch&1)*PVBUF;
        hmma_3pass<4>(buf, buf + TILE_BYTES, buf + 2*TILE_BYTES, buf + 2*TILE_BYTES + BTILE64,
                      i0w, d0w, gid, tig, acc);
        __syncthreads();
    }

#pragma unroll
    for (int nt = 0; nt < 4; nt++) {
        const int d = d0w + nt*8 + tig*2;
#pragma unroll
        for (int mt = 0; mt < 2; mt++) {
#pragma unroll
            for (int half = 0; half < 2; half++) {
                const int row = m0 + i0w + mt*16 + gid + half*8;
                float v0 = acc[mt][nt][half*2+0];
                float v1 = acc[mt][nt][half*2+1];
                __nv_bfloat16 h0,l0,h1,l1;
                bf16_split(v0,h0,l0); bf16_split(v1,h1,l1);
                size_t o = ((size_t)(b*SEQ + row))*D_MODEL + h*DH + d;
                *reinterpret_cast<uint32_t*>(g_Xh + o) = pack2(h0,h1);
                *reinterpret_cast<uint32_t*>(g_Xl + o) = pack2(l0,l1);
            }
        }
    }
}

// ---------------------------------------------------------------------------
extern "C" void kernel_launch(void* const* d_in, const int* in_sizes, int n_in,
                              void* d_out, int out_size)
{
    const float* query = (const float*)d_in[0];
    const float* key   = (const float*)d_in[1];
    const float* value = (const float*)d_in[2];
    const int*   mask  = (const int*)  d_in[3];
    const float* Wq    = (const float*)d_in[4];
    const float* bq    = (const float*)d_in[5];
    const float* Wk    = (const float*)d_in[6];
    const float* bk    = (const float*)d_in[7];
    const float* Wv    = (const float*)d_in[8];
    const float* bv    = (const float*)d_in[9];
    const float* Wo    = (const float*)d_in[10];
    const float* bo    = (const float*)d_in[11];

    float* out = (float*)d_out;
    float* attn_arg = ((long long)out_size >= (long long)OUT_ELEMS + ATTN_ELEMS)
                      ? (out + OUT_ELEMS) : nullptr;

    cudaFuncSetAttribute(qkv_proj_kernel, cudaFuncAttributeMaxDynamicSharedMemorySize, PROJ_SMEM);
    cudaFuncSetAttribute(oproj_kernel,    cudaFuncAttributeMaxDynamicSharedMemorySize, PROJ_SMEM);
    cudaFuncSetAttribute(score_kernel,    cudaFuncAttributeMaxDynamicSharedMemorySize, SCORE_SMEM);
    cudaFuncSetAttribute(pv_kernel,       cudaFuncAttributeMaxDynamicSharedMemorySize, PV_SMEM);

    dim3 blk(256);
    split_kernel   <<<dim3(256, 7), blk>>>(query, key, value, Wq, Wk, Wv, Wo);
    qkv_proj_kernel<<<dim3(4, 32, 3), blk, PROJ_SMEM>>>(bq, bk, bv);
    score_kernel   <<<dim3(16, 16, 16), blk, SCORE_SMEM>>>(mask, attn_arg);
    softmax_kernel <<<dim3(NBH*SEQ), blk>>>(attn_arg);
    pv_kernel      <<<dim3(16, 16), blk, PV_SMEM>>>();
    oproj_kernel   <<<dim3(4, 32), blk, PROJ_SMEM>>>(bo, out);
}